// round 1
// baseline (speedup 1.0000x reference)
#include <cuda_runtime.h>
#include <cstdint>
#include <cstddef>

#define B_ 256
#define L_ 512
#define D_ 768
#define C_ 19
#define CP 20
#define BL (B_*L_)

// Scratch for emissions, padded to 20 floats/row (80B-aligned rows -> 64-bit stores)
__device__ float g_emis[(size_t)BL * CP];

__device__ __forceinline__ unsigned long long pack2(float x){
    unsigned long long r;
    asm("mov.b64 %0, {%1, %1};" : "=l"(r) : "f"(x));
    return r;
}
__device__ __forceinline__ unsigned long long fma2(unsigned long long a,
                                                   unsigned long long b,
                                                   unsigned long long c){
    unsigned long long d;
    asm("fma.rn.f32x2 %0, %1, %2, %3;" : "=l"(d) : "l"(a), "l"(b), "l"(c));
    return d;
}

#define SMEM_A (D_ * 10 * 8)   // 61440 bytes: w2[d][p] packed pairs

// ---------------------------------------------------------------------------
// Kernel A: emissions GEMM. emis[row][c] = sum_d feats[row][d]*W[c][d] + b[c]
// 256 blocks x 256 threads, 2 rows per thread. Packed f32x2 FMA, weights in
// shared as (class 2p, class 2p+1) pairs; LDS is warp-broadcast (all lanes
// same d), amortized over 2 rows.
// ---------------------------------------------------------------------------
__global__ void __launch_bounds__(256) emis_kernel(const float* __restrict__ feats,
                                                   const float* __restrict__ W,
                                                   const float* __restrict__ bias){
    extern __shared__ unsigned long long w2[];   // [768*10]
    int tid = threadIdx.x;
    for (int i = tid; i < D_ * 10; i += 256){
        int d = i / 10, p = i % 10;
        float lo = W[(2*p) * D_ + d];
        float hi = (2*p + 1 < C_) ? W[(2*p + 1) * D_ + d] : 0.f;
        float2 t = make_float2(lo, hi);
        w2[i] = *reinterpret_cast<unsigned long long*>(&t);
    }
    __syncthreads();

    unsigned long long accA[10], accB[10];
#pragma unroll
    for (int p = 0; p < 10; p++){
        float lo = bias[2*p];
        float hi = (2*p + 1 < C_) ? bias[2*p + 1] : 0.f;
        float2 t = make_float2(lo, hi);
        accA[p] = *reinterpret_cast<unsigned long long*>(&t);
        accB[p] = accA[p];
    }

    size_t rowA = (size_t)blockIdx.x * 512 + tid;
    size_t rowB = rowA + 256;
    const float4* fA = reinterpret_cast<const float4*>(feats + rowA * D_);
    const float4* fB = reinterpret_cast<const float4*>(feats + rowB * D_);

    for (int q = 0; q < D_ / 4; q++){
        float4 a = fA[q], b = fB[q];
#pragma unroll
        for (int j = 0; j < 4; j++){
            float av = (&a.x)[j], bv = (&b.x)[j];
            unsigned long long pa = pack2(av), pb = pack2(bv);
            int d = q * 4 + j;
#pragma unroll
            for (int p = 0; p < 10; p++){
                unsigned long long w = w2[d * 10 + p];
                accA[p] = fma2(pa, w, accA[p]);
                accB[p] = fma2(pb, w, accB[p]);
            }
        }
    }

    unsigned long long* oA = reinterpret_cast<unsigned long long*>(g_emis + rowA * CP);
    unsigned long long* oB = reinterpret_cast<unsigned long long*>(g_emis + rowB * CP);
#pragma unroll
    for (int p = 0; p < 10; p++){ oA[p] = accA[p]; oB[p] = accB[p]; }
}

// ---------------------------------------------------------------------------
// Kernel B: Viterbi forward + backtrace. One warp per batch (4 batches/block
// so warps land on all 4 SMSPs). Lane c owns class c: per step, gather all
// 19 scores via SHFL, add T[c][j], first-max tree (leftmost on ties ==
// jnp.argmax), record byte backpointers in shared; backtrace from shared.
// ---------------------------------------------------------------------------
__global__ void __launch_bounds__(128) viterbi_kernel(const float* __restrict__ masks,
                                                      const float* __restrict__ trans,
                                                      float* __restrict__ out){
    __shared__ unsigned char bp_sh[4][L_][CP];
    int w = threadIdx.x >> 5, lane = threadIdx.x & 31;
    int b = blockIdx.x * 4 + w;
    bool active = lane < C_;
    int c = active ? lane : 0;

    float Trow[C_];
#pragma unroll
    for (int j = 0; j < C_; j++) Trow[j] = trans[c * C_ + j];
    float tstop = trans[(C_ - 1) * C_ + c];   // transitions[stop_idx][c]

    const float* eb = g_emis + (size_t)b * L_ * CP;
    const float* mb = masks + (size_t)b * L_;

    float s = (lane == C_ - 2) ? 0.f : -10000.f;   // start_idx = C-2
    float e = active ? eb[lane] : 0.f;
    float m = mb[0];

    for (int t = 0; t < L_; t++){
        // prefetch next step's emission/mask (hide L2 latency off the s-chain)
        float e_n = 0.f, m_n = 1.f;
        if (t + 1 < L_){
            e_n = active ? eb[(t + 1) * CP + lane] : 0.f;
            m_n = mb[t + 1];
        }

        float v[C_];
#pragma unroll
        for (int j = 0; j < C_; j++){
            float sj = __shfl_sync(0xffffffffu, s, j);
            v[j] = sj + Trow[j];
        }
        float bv[C_]; int bidx[C_];
#pragma unroll
        for (int j = 0; j < C_; j++){ bv[j] = v[j]; bidx[j] = j; }
#pragma unroll
        for (int stp = 1; stp < C_; stp <<= 1){
#pragma unroll
            for (int j = 0; j + stp < C_; j += (stp << 1)){
                bool g = bv[j + stp] > bv[j];      // strict > : leftmost wins ties
                bv[j]   = g ? bv[j + stp] : bv[j];
                bidx[j] = g ? bidx[j + stp] : bidx[j];
            }
        }
        float mx = bv[0];
        int bp = bidx[0];

        float acc = mx + e;
        float ns = acc * m + s * (1.0f - m);       // exact reference blend
        s = ns;
        if (active) bp_sh[w][t][lane] = (unsigned char)bp;

        e = e_n; m = m_n;
    }

    // final = s + transitions[stop_idx][c]; best (max, first-index argmax)
    float fv = active ? (s + tstop) : -3.4e38f;
    int fi = active ? lane : 999;
#pragma unroll
    for (int off = 16; off > 0; off >>= 1){
        float ov = __shfl_down_sync(0xffffffffu, fv, off);
        int oi = __shfl_down_sync(0xffffffffu, fi, off);
        if (ov > fv || (ov == fv && oi < fi)){ fv = ov; fi = oi; }
    }
    __syncwarp();

    if (lane == 0){
        out[b] = fv;
        int cur = fi;
        float* po = out + B_ + (size_t)b * L_;
        for (int t = L_ - 1; t >= 0; t--){
            float mt = mb[t];
            bool valid = mt > 0.f;
            po[t] = valid ? (float)cur : -1.f;
            if (valid) cur = bp_sh[w][t][cur];
        }
    }
}

// ---------------------------------------------------------------------------
extern "C" void kernel_launch(void* const* d_in, const int* in_sizes, int n_in,
                              void* d_out, int out_size){
    const float* feats = (const float*)d_in[0];
    const float* masks = (const float*)d_in[1];
    const float* W     = (const float*)d_in[2];
    const float* bias  = (const float*)d_in[3];
    const float* trans = (const float*)d_in[4];
    float* out = (float*)d_out;

    cudaFuncSetAttribute(emis_kernel, cudaFuncAttributeMaxDynamicSharedMemorySize, SMEM_A);
    emis_kernel<<<256, 256, SMEM_A>>>(feats, W, bias);
    viterbi_kernel<<<B_ / 4, 128>>>(masks, trans, out);
}

// round 2
// speedup vs baseline: 1.4255x; 1.4255x over previous
#include <cuda_runtime.h>
#include <cstdint>
#include <cstddef>

#define B_ 256
#define L_ 512
#define D_ 768
#define C_ 19
#define CP 20
#define BL (B_*L_)

// Emission scratch, padded to 20 floats/row (64-bit aligned stores)
__device__ float g_emis[(size_t)BL * CP];

__device__ __forceinline__ unsigned long long pack2(float x){
    unsigned long long r;
    asm("mov.b64 %0, {%1, %1};" : "=l"(r) : "f"(x));
    return r;
}
__device__ __forceinline__ unsigned long long fma2(unsigned long long a,
                                                   unsigned long long b,
                                                   unsigned long long c){
    unsigned long long d;
    asm("fma.rn.f32x2 %0, %1, %2, %3;" : "=l"(d) : "l"(a), "l"(b), "l"(c));
    return d;
}

#define SMEM_A (D_ * 10 * 8)   // 61440 bytes: w2[d][p] packed class pairs

// ---------------------------------------------------------------------------
// Kernel A: emissions. 128 blocks x 256 threads, 4 rows/thread -> single wave,
// weight LDS.64 amortized over 4 accumulator sets. Packed f32x2 FMA throughout.
// ---------------------------------------------------------------------------
__global__ void __launch_bounds__(256) emis_kernel(const float* __restrict__ feats,
                                                   const float* __restrict__ W,
                                                   const float* __restrict__ bias){
    extern __shared__ unsigned long long w2[];   // [768*10]
    int tid = threadIdx.x;
    for (int i = tid; i < D_ * 10; i += 256){
        int d = i / 10, p = i % 10;
        float lo = W[(2*p) * D_ + d];
        float hi = (2*p + 1 < C_) ? W[(2*p + 1) * D_ + d] : 0.f;
        float2 t = make_float2(lo, hi);
        w2[i] = *reinterpret_cast<unsigned long long*>(&t);
    }
    __syncthreads();

    unsigned long long acc[4][10];
#pragma unroll
    for (int p = 0; p < 10; p++){
        float lo = bias[2*p];
        float hi = (2*p + 1 < C_) ? bias[2*p + 1] : 0.f;
        float2 t = make_float2(lo, hi);
        unsigned long long bv = *reinterpret_cast<unsigned long long*>(&t);
#pragma unroll
        for (int r = 0; r < 4; r++) acc[r][p] = bv;
    }

    size_t base = (size_t)blockIdx.x * 1024 + tid;
    const float4* f0 = reinterpret_cast<const float4*>(feats + (base        ) * D_);
    const float4* f1 = reinterpret_cast<const float4*>(feats + (base +  256 ) * D_);
    const float4* f2 = reinterpret_cast<const float4*>(feats + (base +  512 ) * D_);
    const float4* f3 = reinterpret_cast<const float4*>(feats + (base +  768 ) * D_);

    for (int q = 0; q < D_ / 4; q++){
        float4 a = f0[q], b = f1[q], c = f2[q], dd = f3[q];
#pragma unroll
        for (int j = 0; j < 4; j++){
            unsigned long long p0 = pack2((&a.x)[j]);
            unsigned long long p1 = pack2((&b.x)[j]);
            unsigned long long p2 = pack2((&c.x)[j]);
            unsigned long long p3 = pack2((&dd.x)[j]);
            int d = q * 4 + j;
#pragma unroll
            for (int p = 0; p < 10; p++){
                unsigned long long w = w2[d * 10 + p];
                acc[0][p] = fma2(p0, w, acc[0][p]);
                acc[1][p] = fma2(p1, w, acc[1][p]);
                acc[2][p] = fma2(p2, w, acc[2][p]);
                acc[3][p] = fma2(p3, w, acc[3][p]);
            }
        }
    }

#pragma unroll
    for (int r = 0; r < 4; r++){
        unsigned long long* o =
            reinterpret_cast<unsigned long long*>(g_emis + (base + (size_t)r * 256) * CP);
#pragma unroll
        for (int p = 0; p < 10; p++) o[p] = acc[r][p];
    }
}

// ---------------------------------------------------------------------------
// Kernel B: Viterbi forward + backtrace. One warp per batch, lane c owns class
// c. Per step: 19 SHFL gathers, FADD, FMNMX max-tree (critical path), argmax
// via equality bitmask + ffs (off critical path, leftmost tie == jnp.argmax).
// Emissions prefetched 4 steps deep; masks staged in shared (kills serial LDG
// in backtrace). Tags staged in spare byte of padded bp rows, written
// coalesced at the end.
// ---------------------------------------------------------------------------
__global__ void __launch_bounds__(128) viterbi_kernel(const float* __restrict__ masks,
                                                      const float* __restrict__ trans,
                                                      float* __restrict__ out){
    __shared__ signed char bp_sh[4][L_][CP];   // [..][19] reused for tags
    __shared__ float m_sh[4][L_];
    int w = threadIdx.x >> 5, lane = threadIdx.x & 31;
    int b = blockIdx.x * 4 + w;
    bool active = lane < C_;
    int c = active ? lane : 0;

    float Trow[C_];
#pragma unroll
    for (int j = 0; j < C_; j++) Trow[j] = trans[c * C_ + j];
    float tstop = trans[(C_ - 1) * C_ + c];

    const float* eb = g_emis + (size_t)b * L_ * CP;
    const float* mb = masks + (size_t)b * L_;

    // stage masks to shared
    for (int i = lane; i < L_; i += 32) m_sh[w][i] = mb[i];
    __syncwarp();

    float s = (lane == C_ - 2) ? 0.f : -10000.f;

    int ld_lane = active ? lane : 0;
    float e0 = eb[0 * CP + ld_lane];
    float e1 = eb[1 * CP + ld_lane];
    float e2 = eb[2 * CP + ld_lane];
    float e3 = eb[3 * CP + ld_lane];

#define VSTEP(T, EREG)                                                         \
    {                                                                          \
        float v[C_];                                                           \
        _Pragma("unroll")                                                      \
        for (int j = 0; j < C_; j++)                                           \
            v[j] = __shfl_sync(0xffffffffu, s, j) + Trow[j];                   \
        float bv[C_];                                                          \
        _Pragma("unroll")                                                      \
        for (int j = 0; j < C_; j++) bv[j] = v[j];                             \
        _Pragma("unroll")                                                      \
        for (int stp = 1; stp < C_; stp <<= 1){                                \
            _Pragma("unroll")                                                  \
            for (int j = 0; j + stp < C_; j += (stp << 1))                     \
                bv[j] = fmaxf(bv[j], bv[j + stp]);                             \
        }                                                                      \
        float mx = bv[0];                                                      \
        float m = m_sh[w][T];                                                  \
        float om = 1.0f - m;                                                   \
        float acc = mx + (EREG);                                               \
        float ns = acc * m;                                                    \
        ns = fmaf(s, om, ns);                                                  \
        unsigned bits = 0;                                                     \
        _Pragma("unroll")                                                      \
        for (int j = 0; j < C_; j++)                                           \
            if (v[j] == mx) bits |= (1u << j);                                 \
        if (active) bp_sh[w][T][lane] = (signed char)(__ffs(bits) - 1);        \
        s = ns;                                                                \
    }

    for (int t = 0; t < L_; t += 4){
        VSTEP(t, e0);     e0 = (t + 4 < L_) ? eb[(t + 4) * CP + ld_lane] : 0.f;
        VSTEP(t + 1, e1); e1 = (t + 5 < L_) ? eb[(t + 5) * CP + ld_lane] : 0.f;
        VSTEP(t + 2, e2); e2 = (t + 6 < L_) ? eb[(t + 6) * CP + ld_lane] : 0.f;
        VSTEP(t + 3, e3); e3 = (t + 7 < L_) ? eb[(t + 7) * CP + ld_lane] : 0.f;
    }
#undef VSTEP

    // final = s + transitions[stop]; first-index argmax across lanes
    float fv = active ? (s + tstop) : -3.4e38f;
    int fi = active ? lane : 999;
#pragma unroll
    for (int off = 16; off > 0; off >>= 1){
        float ov = __shfl_down_sync(0xffffffffu, fv, off);
        int oi = __shfl_down_sync(0xffffffffu, fi, off);
        if (ov > fv || (ov == fv && oi < fi)){ fv = ov; fi = oi; }
    }

    if (lane == 0){
        out[b] = fv;
        int cur = fi;
        for (int t = L_ - 1; t >= 0; t--){
            float mt = m_sh[w][t];
            bool valid = mt > 0.f;
            bp_sh[w][t][C_] = valid ? (signed char)cur : (signed char)(-1);
            if (valid) cur = bp_sh[w][t][cur];
        }
    }
    __syncwarp();

    // coalesced tag write
    float* po = out + B_ + (size_t)b * L_;
    for (int i = lane; i < L_; i += 32)
        po[i] = (float)bp_sh[w][i][C_];
}

// ---------------------------------------------------------------------------
extern "C" void kernel_launch(void* const* d_in, const int* in_sizes, int n_in,
                              void* d_out, int out_size){
    const float* feats = (const float*)d_in[0];
    const float* masks = (const float*)d_in[1];
    const float* W     = (const float*)d_in[2];
    const float* bias  = (const float*)d_in[3];
    const float* trans = (const float*)d_in[4];
    float* out = (float*)d_out;

    cudaFuncSetAttribute(emis_kernel, cudaFuncAttributeMaxDynamicSharedMemorySize, SMEM_A);
    emis_kernel<<<128, 256, SMEM_A>>>(feats, W, bias);
    viterbi_kernel<<<B_ / 4, 128>>>(masks, trans, out);
}